// round 10
// baseline (speedup 1.0000x reference)
#include <cuda_runtime.h>
#include <cuda_bf16.h>
#include <math.h>
#include <math_constants.h>
#include <stdint.h>

// Problem constants
#define BSZ 2
#define TSEQ 2048
#define CDIM 1024
#define NHEAD 16
#define DHEAD 64
#define MROWS (BSZ * TSEQ)          // 4096
#define QKVCOLS (3 * CDIM)          // 3072

// ---------------------------------------------------------------------------
// Scratch
// ---------------------------------------------------------------------------
__device__ float g_qkv[(size_t)MROWS * QKVCOLS];
__device__ float g_xf[(size_t)MROWS * CDIM];          // x, A-frag order, tf32
__device__ float g_waf[(size_t)CDIM * QKVCOLS];       // w_attn, paired B-frag, tf32
__device__ float g_wpf[(size_t)CDIM * CDIM];          // w_proj, paired B-frag, tf32
__device__ float g_yf[(size_t)MROWS * CDIM];          // y, A-frag order, tf32
__device__ __nv_bfloat16 g_qh[(size_t)BSZ * NHEAD * TSEQ * DHEAD];
__device__ __nv_bfloat16 g_ql[(size_t)BSZ * NHEAD * TSEQ * DHEAD];
__device__ __nv_bfloat16 g_kh[(size_t)BSZ * NHEAD * TSEQ * DHEAD];
__device__ __nv_bfloat16 g_kl[(size_t)BSZ * NHEAD * TSEQ * DHEAD];
__device__ __nv_bfloat16 g_vth[(size_t)BSZ * NHEAD * DHEAD * TSEQ];  // [bh][d][t]
__device__ __nv_bfloat16 g_vtl[(size_t)BSZ * NHEAD * DHEAD * TSEQ];
__device__ float2 g_rope[TSEQ * (DHEAD / 2)];

// ---------------------------------------------------------------------------
// RoPE table
// ---------------------------------------------------------------------------
__global__ void build_rope_kernel(float2* __restrict__ table) {
    int i = blockIdx.x * blockDim.x + threadIdx.x;
    if (i >= TSEQ * 32) return;
    int t = i >> 5;
    int j = i & 31;
    double inv = pow(10000.0, -(double)j / 32.0);
    double ang = (double)t * inv;
    table[i] = make_float2((float)cos(ang), (float)sin(ang));
}

// ---------------------------------------------------------------------------
// Math helpers
// ---------------------------------------------------------------------------
__device__ __forceinline__ uint32_t f2tf32(float x) {
    uint32_t r;
    asm("cvt.rna.tf32.f32 %0, %1;" : "=r"(r) : "f"(x));
    return r;
}
__device__ __forceinline__ float tf32f(float x) {
    return __uint_as_float(f2tf32(x));
}
__device__ __forceinline__ float ex2f(float x) {
    float r;
    asm("ex2.approx.ftz.f32 %0, %1;" : "=f"(r) : "f"(x));
    return r;
}
__device__ __forceinline__ void mma_tf32(float c[4], uint32_t a0, uint32_t a1,
                                         uint32_t a2, uint32_t a3,
                                         uint32_t b0, uint32_t b1) {
    asm volatile(
        "mma.sync.aligned.m16n8k8.row.col.f32.tf32.tf32.f32 "
        "{%0,%1,%2,%3}, {%4,%5,%6,%7}, {%8,%9}, {%0,%1,%2,%3};\n"
        : "+f"(c[0]), "+f"(c[1]), "+f"(c[2]), "+f"(c[3])
        : "r"(a0), "r"(a1), "r"(a2), "r"(a3), "r"(b0), "r"(b1));
}
__device__ __forceinline__ void mma_bf16(float c[4], uint32_t a0, uint32_t a1,
                                         uint32_t a2, uint32_t a3,
                                         uint32_t b0, uint32_t b1) {
    asm volatile(
        "mma.sync.aligned.m16n8k16.row.col.f32.bf16.bf16.f32 "
        "{%0,%1,%2,%3}, {%4,%5,%6,%7}, {%8,%9}, {%0,%1,%2,%3};\n"
        : "+f"(c[0]), "+f"(c[1]), "+f"(c[2]), "+f"(c[3])
        : "r"(a0), "r"(a1), "r"(a2), "r"(a3), "r"(b0), "r"(b1));
}
__device__ __forceinline__ void ldsm_x4(uint32_t& r0, uint32_t& r1,
                                        uint32_t& r2, uint32_t& r3,
                                        uint32_t addr) {
    asm volatile(
        "ldmatrix.sync.aligned.m8n8.x4.shared.b16 {%0,%1,%2,%3}, [%4];"
        : "=r"(r0), "=r"(r1), "=r"(r2), "=r"(r3) : "r"(addr));
}
__device__ __forceinline__ void packsplit2(float p0, float p1,
                                           uint32_t& hi, uint32_t& lo) {
    __nv_bfloat162 h = __floats2bfloat162_rn(p0, p1);
    float2 f = __bfloat1622float2(h);
    __nv_bfloat162 l = __floats2bfloat162_rn(p0 - f.x, p1 - f.y);
    hi = *reinterpret_cast<uint32_t*>(&h);
    lo = *reinterpret_cast<uint32_t*>(&l);
}
__device__ __forceinline__ uint32_t smem_u32(const void* p) {
    uint32_t a;
    asm("{ .reg .u64 t; cvta.to.shared.u64 t, %1; cvt.u32.u64 %0, t; }"
        : "=r"(a) : "l"(p));
    return a;
}
__device__ __forceinline__ void cp16(uint32_t smem, const void* g) {
    asm volatile("cp.async.ca.shared.global [%0], [%1], 16;"
                 :: "r"(smem), "l"(g) : "memory");
}
#define CP_COMMIT() asm volatile("cp.async.commit_group;" ::: "memory")
#define CP_WAIT0() asm volatile("cp.async.wait_group 0;" ::: "memory")
#define CP_WAIT1() asm volatile("cp.async.wait_group 1;" ::: "memory")
#define CP_WAIT2() asm volatile("cp.async.wait_group 2;" ::: "memory")

// ---------------------------------------------------------------------------
// A-fragment reorder + tf32 round: [M][K] -> [M/16][K/8][32][4]
// ---------------------------------------------------------------------------
__global__ void afrag_kernel(const float* __restrict__ in,
                             float* __restrict__ out, int K) {
    int idx = blockIdx.x * 256 + threadIdx.x;
    int lane = idx & 31;
    int blk = idx >> 5;
    int KB = K >> 3;
    int cb = blk % KB, rb = blk / KB;
    int g = lane >> 2, tig = lane & 3;
    const float* p = in + (size_t)(rb * 16 + g) * K + cb * 8 + tig;
    float4 v;
    v.x = tf32f(p[0]);
    v.y = tf32f(p[(size_t)8 * K]);
    v.z = tf32f(p[4]);
    v.w = tf32f(p[(size_t)8 * K + 4]);
    ((float4*)out)[idx] = v;
}

// ---------------------------------------------------------------------------
// Paired B-fragment reorder + tf32 round: [K][N] -> [K/8][N/16][32][4]
// lane (g,tig): {B[kb8+tig][n0+g], B[kb8+4+tig][n0+g],
//                B[kb8+tig][n0+8+g], B[kb8+4+tig][n0+8+g]}
// ---------------------------------------------------------------------------
__global__ void bfrag2_kernel(const float* __restrict__ in,
                              float* __restrict__ out, int N) {
    int idx = blockIdx.x * 256 + threadIdx.x;
    int lane = idx & 31;
    int blk = idx >> 5;
    int NB2 = N >> 4;
    int nbp = blk % NB2, kb = blk / NB2;
    int g = lane >> 2, tig = lane & 3;
    const float* p = in + (size_t)(kb * 8 + tig) * N + nbp * 16 + g;
    float4 v;
    v.x = tf32f(p[0]);
    v.y = tf32f(p[(size_t)4 * N]);
    v.z = tf32f(p[8]);
    v.w = tf32f(p[(size_t)4 * N + 8]);
    ((float4*)out)[idx] = v;
}

// ---------------------------------------------------------------------------
// TF32 GEMM v4: fragment-order operands, paired B (LDS.128), 3-stage cp.async.
// C[M,N] = A@B + bias. 128x128x32 tile, 256 thr (8 warps, 2m x 4n).
// Smem: 3 stages x (A 16KB + B 16KB) = 96KB.
// ---------------------------------------------------------------------------
#define GEMM_SMEM_BYTES 98304

__global__ __launch_bounds__(256, 2)
void gemm_tf32_kernel(const float* __restrict__ Af, const float* __restrict__ Bf,
                      const float* __restrict__ bias, float* __restrict__ C,
                      int M, int N, int K) {
    extern __shared__ float sm[];
    const uint32_t smb = smem_u32(sm);
    const int tid = threadIdx.x;
    const int lane = tid & 31;
    const int warp = tid >> 5;
    const int wm = warp >> 2;
    const int wn = warp & 3;
    const int g = lane >> 2;
    const int tig = lane & 3;
    const int row0 = blockIdx.y * 128;
    const int col0 = blockIdx.x * 128;
    const int KB = K >> 3;
    const int NB2 = N >> 4;
    const int rb0 = row0 >> 4;
    const int nbp0 = col0 >> 4;

    float acc[4][4][4];
#pragma unroll
    for (int im = 0; im < 4; im++)
#pragma unroll
        for (int in = 0; in < 4; in++)
#pragma unroll
            for (int r = 0; r < 4; r++) acc[im][in][r] = 0.0f;

    // loader maps (per stage: A 1024 x 16B units, B 1024 x 16B units)
    int a_rblk[4], a_kblk[4], a_l16[4];
    int b_kblk[4], b_nbp[4], b_l16[4];
#pragma unroll
    for (int s = 0; s < 4; s++) {
        int u = tid + s * 256;
        int ablk = u >> 5;
        a_rblk[s] = ablk >> 2;
        a_kblk[s] = ablk & 3;
        a_l16[s] = u & 31;
        b_kblk[s] = u >> 8;
        b_nbp[s] = (u >> 5) & 7;
        b_l16[s] = u & 31;
    }

    const int nT = K / 32;

    // issue stage helper (inline twice for prologue, once in loop)
#define GEMM_ISSUE(tt) do {                                                    \
        const int kbg = (tt) * 4;                                              \
        const int st = (tt) % 3;                                               \
        const uint32_t ao = (uint32_t)(st * 16384);                            \
        const uint32_t bo = 49152u + (uint32_t)(st * 16384);                   \
        _Pragma("unroll")                                                      \
        for (int s = 0; s < 4; s++) {                                          \
            cp16(smb + ao + (uint32_t)((a_rblk[s] * 4 + a_kblk[s]) * 512 + a_l16[s] * 16), \
                 Af + (((size_t)(rb0 + a_rblk[s]) * KB + kbg + a_kblk[s]) << 7) + a_l16[s] * 4); \
            cp16(smb + bo + (uint32_t)((b_kblk[s] * 8 + b_nbp[s]) * 512 + b_l16[s] * 16), \
                 Bf + (((size_t)(kbg + b_kblk[s]) * NB2 + nbp0 + b_nbp[s]) << 7) + b_l16[s] * 4); \
        }                                                                      \
        CP_COMMIT();                                                           \
    } while (0)

    GEMM_ISSUE(0);
    GEMM_ISSUE(1);

    for (int t = 0; t < nT; t++) {
        if (t + 2 < nT) {
            GEMM_ISSUE(t + 2);
            CP_WAIT2();
        } else if (t + 1 < nT) {
            CP_WAIT1();
        } else {
            CP_WAIT0();
        }
        __syncthreads();

        const float* As = sm + (t % 3) * 4096;
        const float* Bs = sm + 12288 + (t % 3) * 4096;

#pragma unroll
        for (int kk = 0; kk < 4; kk++) {
            float4 af[4];
#pragma unroll
            for (int im = 0; im < 4; im++)
                af[im] = *(const float4*)(As + ((wm * 4 + im) * 4 + kk) * 128 + lane * 4);
            float4 b4[2];
#pragma unroll
            for (int p = 0; p < 2; p++)
                b4[p] = *(const float4*)(Bs + (kk * 8 + wn * 2 + p) * 128 + lane * 4);
#pragma unroll
            for (int im = 0; im < 4; im++) {
#pragma unroll
                for (int p = 0; p < 2; p++) {
                    mma_tf32(acc[im][2 * p],
                             __float_as_uint(af[im].x), __float_as_uint(af[im].y),
                             __float_as_uint(af[im].z), __float_as_uint(af[im].w),
                             __float_as_uint(b4[p].x), __float_as_uint(b4[p].y));
                    mma_tf32(acc[im][2 * p + 1],
                             __float_as_uint(af[im].x), __float_as_uint(af[im].y),
                             __float_as_uint(af[im].z), __float_as_uint(af[im].w),
                             __float_as_uint(b4[p].z), __float_as_uint(b4[p].w));
                }
            }
        }
        __syncthreads();
    }

    // epilogue: rows g + {0,8}, cols 2*tig + {0,1}
#pragma unroll
    for (int im = 0; im < 4; im++) {
        int r = row0 + wm * 64 + im * 16 + g;
#pragma unroll
        for (int in = 0; in < 4; in++) {
            int c = col0 + wn * 32 + in * 8 + tig * 2;
            float b0 = bias[c], b1 = bias[c + 1];
            float2 v0 = make_float2(acc[im][in][0] + b0, acc[im][in][1] + b1);
            float2 v1 = make_float2(acc[im][in][2] + b0, acc[im][in][3] + b1);
            *(float2*)&C[(size_t)r * N + c] = v0;
            *(float2*)&C[(size_t)(r + 8) * N + c] = v1;
        }
    }
#undef GEMM_ISSUE
}

// ---------------------------------------------------------------------------
// RoPE + scatter + splits + V transpose (unchanged)
// ---------------------------------------------------------------------------
__global__ __launch_bounds__(256)
void rope_scatter_split_kernel(const float* __restrict__ qkv,
                               const float2* __restrict__ rope,
                               __nv_bfloat16* __restrict__ qh,
                               __nv_bfloat16* __restrict__ ql,
                               __nv_bfloat16* __restrict__ kh,
                               __nv_bfloat16* __restrict__ kl,
                               __nv_bfloat16* __restrict__ vth,
                               __nv_bfloat16* __restrict__ vtl) {
    __shared__ __nv_bfloat16 vsh[64][66];
    __shared__ __nv_bfloat16 vsl[64][66];

    int bh = blockIdx.y;
    int tb = blockIdx.x * 64;
    int b = bh >> 4;
    int h = bh & 15;
    int tid = threadIdx.x;

    const float SCL = 0.125f * 1.4426950408889634f;

#pragma unroll
    for (int e = 0; e < 16; e++) {
        int idx = tid + e * 256;
        int tl = idx >> 6;
        int d = idx & 63;
        int t = tb + tl;
        size_t base = (size_t)(b * TSEQ + t) * QKVCOLS + h * DHEAD;
        float2 cs = rope[t * 32 + (d & 31)];

        float qv = qkv[base + d];
        float kv = qkv[base + CDIM + d];
        float vv = qkv[base + 2 * CDIM + d];
        int dp = (d < 32) ? d + 32 : d - 32;
        float sgn = (d < 32) ? -1.0f : 1.0f;
        float qr = qkv[base + dp];
        float kr = qkv[base + CDIM + dp];

        float qrot = (qv * cs.x + sgn * qr * cs.y) * SCL;
        float krot = kv * cs.x + sgn * kr * cs.y;

        size_t o = ((size_t)bh * TSEQ + t) * DHEAD + d;
        __nv_bfloat16 qhv = __float2bfloat16(qrot);
        __nv_bfloat16 khv = __float2bfloat16(krot);
        qh[o] = qhv;
        ql[o] = __float2bfloat16(qrot - __bfloat162float(qhv));
        kh[o] = khv;
        kl[o] = __float2bfloat16(krot - __bfloat162float(khv));

        __nv_bfloat16 vhv = __float2bfloat16(vv);
        vsh[d][tl] = vhv;
        vsl[d][tl] = __float2bfloat16(vv - __bfloat162float(vhv));
    }
    __syncthreads();
#pragma unroll
    for (int e = 0; e < 16; e++) {
        int idx = tid + e * 256;
        int d = idx >> 6;
        int tl = idx & 63;
        size_t o = ((size_t)bh * DHEAD + d) * TSEQ + tb + tl;
        vth[o] = vsh[d][tl];
        vtl[o] = vsl[d][tl];
    }
}

// ---------------------------------------------------------------------------
// Flash attention v5: ldmatrix loads; epilogue writes y directly in
// A-fragment order + tf32 round (kills the afrag(y) pass).
// ---------------------------------------------------------------------------
#define FRS 144
#define OFF_KH 0
#define OFF_KL 9216
#define OFF_VTH 18432
#define OFF_VTL 27648
#define BUFB 36864
#define FLASH_SMEM_BYTES (2 * BUFB)

#define NEGBIG (-1e30f)

__global__ __launch_bounds__(128, 3)
void flash_mma_kernel(const __nv_bfloat16* __restrict__ QH,
                      const __nv_bfloat16* __restrict__ QL,
                      const __nv_bfloat16* __restrict__ KH,
                      const __nv_bfloat16* __restrict__ KL,
                      const __nv_bfloat16* __restrict__ VTH,
                      const __nv_bfloat16* __restrict__ VTL) {
    extern __shared__ char smc[];
    const uint32_t smb = smem_u32(smc);

    int bh = blockIdx.y;
    int qt = gridDim.x - 1 - blockIdx.x;
    int q0 = qt * 64;

    int tid = threadIdx.x;
    int lane = tid & 31;
    int w = tid >> 5;
    int g = lane >> 2;
    int tig = lane & 3;
    const int r0 = w * 16 + g;

    const int jj = lane & 7;
    const uint32_t ldsm_base =
        (uint32_t)((jj + ((lane >> 4) & 1) * 8) * FRS + ((lane >> 3) & 1) * 16);

    const __nv_bfloat16* KHg = KH + (size_t)bh * TSEQ * DHEAD;
    const __nv_bfloat16* KLg = KL + (size_t)bh * TSEQ * DHEAD;
    const __nv_bfloat16* VTHg = VTH + (size_t)bh * DHEAD * TSEQ;
    const __nv_bfloat16* VTLg = VTL + (size_t)bh * DHEAD * TSEQ;

    {
#pragma unroll
        for (int s = 0; s < 4; s++) {
            int f = tid + s * 128;
            int r = f >> 3;
            int c = (f & 7) * 8;
            uint32_t ro = (uint32_t)(r * FRS + c * 2);
            cp16(smb + OFF_KH + ro, KHg + (size_t)r * DHEAD + c);
            cp16(smb + OFF_KL + ro, KLg + (size_t)r * DHEAD + c);
            cp16(smb + OFF_VTH + ro, VTHg + (size_t)r * TSEQ + c);
            cp16(smb + OFF_VTL + ro, VTLg + (size_t)r * TSEQ + c);
        }
        CP_COMMIT();
    }

    uint32_t qah[4][4], qal[4][4];
    {
        const __nv_bfloat16* Qhg = QH + ((size_t)bh * TSEQ + q0 + r0) * DHEAD;
        const __nv_bfloat16* Qlg = QL + ((size_t)bh * TSEQ + q0 + r0) * DHEAD;
#pragma unroll
        for (int ks = 0; ks < 4; ks++) {
            int c0 = ks * 16 + 2 * tig;
            qah[ks][0] = *(const uint32_t*)(Qhg + c0);
            qah[ks][1] = *(const uint32_t*)(Qhg + 8 * DHEAD + c0);
            qah[ks][2] = *(const uint32_t*)(Qhg + c0 + 8);
            qah[ks][3] = *(const uint32_t*)(Qhg + 8 * DHEAD + c0 + 8);
            qal[ks][0] = *(const uint32_t*)(Qlg + c0);
            qal[ks][1] = *(const uint32_t*)(Qlg + 8 * DHEAD + c0);
            qal[ks][2] = *(const uint32_t*)(Qlg + c0 + 8);
            qal[ks][3] = *(const uint32_t*)(Qlg + 8 * DHEAD + c0 + 8);
        }
    }

    float oacc[8][4];
#pragma unroll
    for (int db = 0; db < 8; db++)
#pragma unroll
        for (int r = 0; r < 4; r++) oacc[db][r] = 0.0f;
    float m0 = NEGBIG, m1 = NEGBIG, l0 = 0.0f, l1 = 0.0f;

    for (int jt = 0; jt <= qt; jt++) {
        CP_WAIT0();
        __syncthreads();

        if (jt < qt) {
            int k0n = (jt + 1) * 64;
            uint32_t nb_ = smb + ((jt + 1) & 1) * BUFB;
#pragma unroll
            for (int s = 0; s < 4; s++) {
                int f = tid + s * 128;
                int r = f >> 3;
                int c = (f & 7) * 8;
                uint32_t ro = (uint32_t)(r * FRS + c * 2);
                cp16(nb_ + OFF_KH + ro, KHg + (size_t)(k0n + r) * DHEAD + c);
                cp16(nb_ + OFF_KL + ro, KLg + (size_t)(k0n + r) * DHEAD + c);
                cp16(nb_ + OFF_VTH + ro, VTHg + (size_t)r * TSEQ + k0n + c);
                cp16(nb_ + OFF_VTL + ro, VTLg + (size_t)r * TSEQ + k0n + c);
            }
            CP_COMMIT();
        }

        const uint32_t bufa = smb + (jt & 1) * BUFB + ldsm_base;

        float sacc[8][4];
#pragma unroll
        for (int nb = 0; nb < 8; nb++)
#pragma unroll
            for (int r = 0; r < 4; r++) sacc[nb][r] = 0.0f;

#pragma unroll
        for (int ks = 0; ks < 4; ks++) {
            const uint32_t ko = (uint32_t)(ks * 32);
#pragma unroll
            for (int nbp = 0; nbp < 4; nbp++) {
                const uint32_t ba = bufa + (uint32_t)(nbp * 16 * FRS) + ko;
                uint32_t h0, h1, h2, h3, e0, e1, e2, e3;
                ldsm_x4(h0, h1, h2, h3, ba + OFF_KH);
                ldsm_x4(e0, e1, e2, e3, ba + OFF_KL);
                mma_bf16(sacc[2 * nbp], qah[ks][0], qah[ks][1], qah[ks][2], qah[ks][3], h0, h1);
                mma_bf16(sacc[2 * nbp], qah[ks][0], qah[ks][1], qah[ks][2], qah[ks][3], e0, e1);
                mma_bf16(sacc[2 * nbp], qal[ks][0], qal[ks][1], qal[ks][2], qal[ks][3], h0, h1);
                mma_bf16(sacc[2 * nbp + 1], qah[ks][0], qah[ks][1], qah[ks][2], qah[ks][3], h2, h3);
                mma_bf16(sacc[2 * nbp + 1], qah[ks][0], qah[ks][1], qah[ks][2], qah[ks][3], e2, e3);
                mma_bf16(sacc[2 * nbp + 1], qal[ks][0], qal[ks][1], qal[ks][2], qal[ks][3], h2, h3);
            }
        }

        if (jt == qt) {
#pragma unroll
            for (int nb = 0; nb < 8; nb++) {
                int c0 = nb * 8 + 2 * tig;
#pragma unroll
                for (int e = 0; e < 2; e++) {
                    if (c0 + e > r0) sacc[nb][e] = NEGBIG;
                    if (c0 + e > r0 + 8) sacc[nb][2 + e] = NEGBIG;
                }
            }
        }

        float tm0 = NEGBIG, tm1 = NEGBIG;
#pragma unroll
        for (int nb = 0; nb < 8; nb++) {
            tm0 = fmaxf(tm0, fmaxf(sacc[nb][0], sacc[nb][1]));
            tm1 = fmaxf(tm1, fmaxf(sacc[nb][2], sacc[nb][3]));
        }
        tm0 = fmaxf(tm0, __shfl_xor_sync(0xffffffffu, tm0, 1));
        tm0 = fmaxf(tm0, __shfl_xor_sync(0xffffffffu, tm0, 2));
        tm1 = fmaxf(tm1, __shfl_xor_sync(0xffffffffu, tm1, 1));
        tm1 = fmaxf(tm1, __shfl_xor_sync(0xffffffffu, tm1, 2));

        float mn0 = fmaxf(m0, tm0);
        float mn1 = fmaxf(m1, tm1);
        float corr0 = ex2f(m0 - mn0);
        float corr1 = ex2f(m1 - mn1);
        float rs0 = 0.0f, rs1 = 0.0f;
#pragma unroll
        for (int nb = 0; nb < 8; nb++) {
            sacc[nb][0] = ex2f(sacc[nb][0] - mn0);
            sacc[nb][1] = ex2f(sacc[nb][1] - mn0);
            sacc[nb][2] = ex2f(sacc[nb][2] - mn1);
            sacc[nb][3] = ex2f(sacc[nb][3] - mn1);
            rs0 += sacc[nb][0] + sacc[nb][1];
            rs1 += sacc[nb][2] + sacc[nb][3];
        }
        rs0 += __shfl_xor_sync(0xffffffffu, rs0, 1);
        rs0 += __shfl_xor_sync(0xffffffffu, rs0, 2);
        rs1 += __shfl_xor_sync(0xffffffffu, rs1, 1);
        rs1 += __shfl_xor_sync(0xffffffffu, rs1, 2);

        l0 = l0 * corr0 + rs0;
        l1 = l1 * corr1 + rs1;
        m0 = mn0;
        m1 = mn1;
#pragma unroll
        for (int db = 0; db < 8; db++) {
            oacc[db][0] *= corr0;
            oacc[db][1] *= corr0;
            oacc[db][2] *= corr1;
            oacc[db][3] *= corr1;
        }

#pragma unroll
        for (int ks = 0; ks < 4; ks++) {
            uint32_t ph[4], pl[4];
            packsplit2(sacc[2 * ks][0], sacc[2 * ks][1], ph[0], pl[0]);
            packsplit2(sacc[2 * ks][2], sacc[2 * ks][3], ph[1], pl[1]);
            packsplit2(sacc[2 * ks + 1][0], sacc[2 * ks + 1][1], ph[2], pl[2]);
            packsplit2(sacc[2 * ks + 1][2], sacc[2 * ks + 1][3], ph[3], pl[3]);
            const uint32_t ko = (uint32_t)(ks * 32);
#pragma unroll
            for (int dbp = 0; dbp < 4; dbp++) {
                const uint32_t ba = bufa + (uint32_t)(dbp * 16 * FRS) + ko;
                uint32_t h0, h1, h2, h3, e0, e1, e2, e3;
                ldsm_x4(h0, h1, h2, h3, ba + OFF_VTH);
                ldsm_x4(e0, e1, e2, e3, ba + OFF_VTL);
                mma_bf16(oacc[2 * dbp], ph[0], ph[1], ph[2], ph[3], h0, h1);
                mma_bf16(oacc[2 * dbp], ph[0], ph[1], ph[2], ph[3], e0, e1);
                mma_bf16(oacc[2 * dbp], pl[0], pl[1], pl[2], pl[3], h0, h1);
                mma_bf16(oacc[2 * dbp + 1], ph[0], ph[1], ph[2], ph[3], h2, h3);
                mma_bf16(oacc[2 * dbp + 1], ph[0], ph[1], ph[2], ph[3], e2, e3);
                mma_bf16(oacc[2 * dbp + 1], pl[0], pl[1], pl[2], pl[3], h2, h3);
            }
        }
    }

    // ---- finalize: write y directly in A-fragment order, tf32-rounded ----
    // yf layout [M/16][K/8=128][32][4]; this thread's rows rb=(b*2048+q0)/16+w,
    // row-within g (+8), cols cb=h*8+db, col-within 2*tig (+1).
    float inv0 = 1.0f / l0;
    float inv1 = 1.0f / l1;
    int b = bh >> 4;
    int h = bh & 15;
    const size_t rb = (size_t)((b * TSEQ + q0) >> 4) + w;
    const int lane0 = g * 4 + ((2 * tig) & 3);       // col 2*tig
    const int cbit = tig >> 1;                       // colbit for both cols
#pragma unroll
    for (int db = 0; db < 8; db++) {
        int cb = h * 8 + db;
        size_t base = ((rb * 128 + cb) * 32) * 4;
        g_yf[base + (size_t)lane0 * 4 + 0 + 2 * cbit] = tf32f(oacc[db][0] * inv0);
        g_yf[base + (size_t)(lane0 + 1) * 4 + 0 + 2 * cbit] = tf32f(oacc[db][1] * inv0);
        g_yf[base + (size_t)lane0 * 4 + 1 + 2 * cbit] = tf32f(oacc[db][2] * inv1);
        g_yf[base + (size_t)(lane0 + 1) * 4 + 1 + 2 * cbit] = tf32f(oacc[db][3] * inv1);
    }
}

// ---------------------------------------------------------------------------
// Launch
// ---------------------------------------------------------------------------
extern "C" void kernel_launch(void* const* d_in, const int* in_sizes, int n_in,
                              void* d_out, int out_size) {
    const float* x      = (const float*)d_in[0];
    const float* w_attn = (const float*)d_in[1];
    const float* b_attn = (const float*)d_in[2];
    const float* w_proj = (const float*)d_in[3];
    const float* b_proj = (const float*)d_in[4];
    float* out = (float*)d_out;

    float *qkv, *xf, *waf, *wpf, *yf;
    float2* rope;
    __nv_bfloat16 *qh, *ql, *kh, *kl, *vth, *vtl;
    cudaGetSymbolAddress((void**)&qkv, g_qkv);
    cudaGetSymbolAddress((void**)&xf, g_xf);
    cudaGetSymbolAddress((void**)&waf, g_waf);
    cudaGetSymbolAddress((void**)&wpf, g_wpf);
    cudaGetSymbolAddress((void**)&yf, g_yf);
    cudaGetSymbolAddress((void**)&qh, g_qh);
    cudaGetSymbolAddress((void**)&ql, g_ql);
    cudaGetSymbolAddress((void**)&kh, g_kh);
    cudaGetSymbolAddress((void**)&kl, g_kl);
    cudaGetSymbolAddress((void**)&vth, g_vth);
    cudaGetSymbolAddress((void**)&vtl, g_vtl);
    cudaGetSymbolAddress((void**)&rope, g_rope);

    cudaFuncSetAttribute(gemm_tf32_kernel,
                         cudaFuncAttributeMaxDynamicSharedMemorySize,
                         GEMM_SMEM_BYTES);
    cudaFuncSetAttribute(flash_mma_kernel,
                         cudaFuncAttributeMaxDynamicSharedMemorySize,
                         FLASH_SMEM_BYTES);

    build_rope_kernel<<<(TSEQ * 32 + 255) / 256, 256>>>(rope);

    // fragment-order prep (tf32 rounding fused)
    afrag_kernel<<<(MROWS / 16) * (CDIM / 8) * 32 / 256, 256>>>(x, xf, CDIM);
    bfrag2_kernel<<<(CDIM / 8) * (QKVCOLS / 16) * 32 / 256, 256>>>(w_attn, waf, QKVCOLS);
    bfrag2_kernel<<<(CDIM / 8) * (CDIM / 16) * 32 / 256, 256>>>(w_proj, wpf, CDIM);

    // QKV GEMM
    gemm_tf32_kernel<<<dim3(QKVCOLS / 128, MROWS / 128), 256, GEMM_SMEM_BYTES>>>(
        xf, waf, b_attn, qkv, MROWS, QKVCOLS, CDIM);

    // RoPE + scatter + splits + V transpose
    rope_scatter_split_kernel<<<dim3(TSEQ / 64, BSZ * NHEAD), 256>>>(
        qkv, rope, qh, ql, kh, kl, vth, vtl);

    // Flash attention (writes yf directly in A-fragment order)
    flash_mma_kernel<<<dim3(TSEQ / 64, BSZ * NHEAD), 128, FLASH_SMEM_BYTES>>>(
        qh, ql, kh, kl, vth, vtl);

    // Output projection
    gemm_tf32_kernel<<<dim3(CDIM / 128, MROWS / 128), 256, GEMM_SMEM_BYTES>>>(
        yf, wpf, b_proj, out, MROWS, CDIM, CDIM);
}